// round 2
// baseline (speedup 1.0000x reference)
#include <cuda_runtime.h>
#include <cuda_fp16.h>

// QConv2d: 3x3 conv, B=16, C=32, N=64, H=W=56, stride 1, pad 1.
// Bit-exact emulation of per-k fp16 (E5M10) requantized accumulation:
//   p   = fp16(fp32(a * w))  -> mul.rn.f32x2 (2 lanes) + cvt.rn.f16x2.f32
//   acc = fp16(acc + p)      -> HADD2 (== fp16(fp32 add) by innocuous dbl rounding)
// k order = c*9 + i*3 + j, matching lax.scan order in the reference.
//
// Layout: block = (output row y, batch pair). 448 blocks = 3.03 waves on 148 SMs.
// Thread = (n-pair, 4-px group), covering both batches -> 8 half2 accumulators.
// Input stored in smem as duplicated float2(v,v) so the f32x2 multiply's
// broadcast operand is a single LDS.64 (no MOV packing).

#define TB 448
typedef unsigned long long ull;

#define SW_FLOATS   (288 * 64)            // weights [k][n], fp16-valued fp32
#define SDUP_PAIRS  (2 * 32 * 3 * 58)     // [bt][c][r][xs] duplicated pairs
#define SMEM_BYTES  (SW_FLOATS * 4 + SDUP_PAIRS * 8)   // 73728 + 89088 = 162816

__device__ __forceinline__ ull mul2_rn(ull a, ull b) {
    ull d;
    asm("mul.rn.f32x2 %0, %1, %2;" : "=l"(d) : "l"(a), "l"(b));
    return d;
}
__device__ __forceinline__ __half2 cvt_pair(ull p) {
    unsigned lo, hi, h;
    asm("mov.b64 {%0, %1}, %2;" : "=r"(lo), "=r"(hi) : "l"(p));
    // first source -> upper half; low half must be lane n0 (= p low)
    asm("cvt.rn.f16x2.f32 %0, %1, %2;" : "=r"(h) : "r"(hi), "r"(lo));
    return *reinterpret_cast<__half2*>(&h);
}

__global__ void __launch_bounds__(TB, 1) qconv2d_kernel(
    const float* __restrict__ x,      // [16][32][56][56]
    const float* __restrict__ w,      // [64][32][3][3] = [64][288]
    const float* __restrict__ bias,   // [64]
    float* __restrict__ out)          // [16][64][56][56]
{
    extern __shared__ float sm[];
    float* sw  = sm;                                   // [k=288][n=64]
    ull*   sdp = reinterpret_cast<ull*>(sm + SW_FLOATS); // [bt][c][r][58] dup pairs

    const int y0  = blockIdx.x;   // output row 0..55
    const int bp  = blockIdx.y;   // batch pair 0..7
    const int tid = threadIdx.x;

    // ---- weights: gmem coalesced, transpose to [k][n], quantize to fp16 value ----
    for (int idx = tid; idx < 64 * 288; idx += TB) {
        int n = idx / 288;
        int k = idx % 288;
        sw[k * 64 + n] = __half2float(__float2half_rn(w[idx]));
    }

    // ---- input: rows y0-1..y0+1, 2 batches, 32 ch, x padded to 58, duplicated ----
    for (int idx = tid; idx < SDUP_PAIRS; idx += TB) {
        int bt  = idx / 5568;           // 5568 = 32*3*58
        int r2  = idx % 5568;
        int c   = r2 / 174;             // 174 = 3*58
        int r3  = r2 % 174;
        int r   = r3 / 58;
        int xs  = r3 % 58;
        int yg  = y0 - 1 + r;
        int xg  = xs - 1;
        float v = 0.0f;
        if (yg >= 0 && yg < 56 && xg >= 0 && xg < 56)
            v = x[(((size_t)(2 * bp + bt) * 32 + c) * 56 + yg) * 56 + xg];
        float2 d = make_float2(v, v);
        sdp[idx] = *reinterpret_cast<ull*>(&d);
    }
    __syncthreads();

    const int tn = tid & 31;      // n-pair index: n0 = 2*tn, n1 = 2*tn+1
    const int g  = tid >> 5;      // pixel group 0..13
    const int x0 = g * 4;

    __half2 acc[2][4];
    #pragma unroll
    for (int bt = 0; bt < 2; ++bt)
        #pragma unroll
        for (int p = 0; p < 4; ++p)
            acc[bt][p] = __float2half2_rn(0.0f);

    const float* swt = sw + 2 * tn;

    #pragma unroll 1
    for (int c = 0; c < 32; ++c) {
        #pragma unroll
        for (int i = 0; i < 3; ++i) {
            // weight pairs for j=0,1,2 (row k = c*9 + i*3 + j)
            const float* wr = swt + (c * 9 + i * 3) * 64;
            ull w2[3];
            #pragma unroll
            for (int j = 0; j < 3; ++j)
                w2[j] = *reinterpret_cast<const ull*>(wr + j * 64);

            #pragma unroll
            for (int bt = 0; bt < 2; ++bt) {
                const ull* ar = sdp + ((bt * 32 + c) * 3 + i) * 58 + x0;
                ull d0 = ar[0], d1 = ar[1], d2 = ar[2];
                ull d3 = ar[3], d4 = ar[4], d5 = ar[5];
                // j = 0
                acc[bt][0] = __hadd2(acc[bt][0], cvt_pair(mul2_rn(d0, w2[0])));
                acc[bt][1] = __hadd2(acc[bt][1], cvt_pair(mul2_rn(d1, w2[0])));
                acc[bt][2] = __hadd2(acc[bt][2], cvt_pair(mul2_rn(d2, w2[0])));
                acc[bt][3] = __hadd2(acc[bt][3], cvt_pair(mul2_rn(d3, w2[0])));
                // j = 1
                acc[bt][0] = __hadd2(acc[bt][0], cvt_pair(mul2_rn(d1, w2[1])));
                acc[bt][1] = __hadd2(acc[bt][1], cvt_pair(mul2_rn(d2, w2[1])));
                acc[bt][2] = __hadd2(acc[bt][2], cvt_pair(mul2_rn(d3, w2[1])));
                acc[bt][3] = __hadd2(acc[bt][3], cvt_pair(mul2_rn(d4, w2[1])));
                // j = 2
                acc[bt][0] = __hadd2(acc[bt][0], cvt_pair(mul2_rn(d2, w2[2])));
                acc[bt][1] = __hadd2(acc[bt][1], cvt_pair(mul2_rn(d3, w2[2])));
                acc[bt][2] = __hadd2(acc[bt][2], cvt_pair(mul2_rn(d4, w2[2])));
                acc[bt][3] = __hadd2(acc[bt][3], cvt_pair(mul2_rn(d5, w2[2])));
            }
        }
    }

    // ---- epilogue: out = fp32(fp16(acc + fp16(bias))) ----
    const int n0 = 2 * tn;
    __half2 qb = __halves2half2(__float2half_rn(bias[n0]),
                                __float2half_rn(bias[n0 + 1]));

    #pragma unroll
    for (int bt = 0; bt < 2; ++bt) {
        __half2 r0 = __hadd2(acc[bt][0], qb);
        __half2 r1 = __hadd2(acc[bt][1], qb);
        __half2 r2 = __hadd2(acc[bt][2], qb);
        __half2 r3 = __hadd2(acc[bt][3], qb);

        float4 v0, v1;
        v0.x = __low2float(r0);  v0.y = __low2float(r1);
        v0.z = __low2float(r2);  v0.w = __low2float(r3);
        v1.x = __high2float(r0); v1.y = __high2float(r1);
        v1.z = __high2float(r2); v1.w = __high2float(r3);

        int b = 2 * bp + bt;
        size_t o0 = (((size_t)b * 64 + n0) * 56 + y0) * 56 + x0;
        size_t o1 = (((size_t)b * 64 + n0 + 1) * 56 + y0) * 56 + x0;
        *reinterpret_cast<float4*>(out + o0) = v0;
        *reinterpret_cast<float4*>(out + o1) = v1;
    }
}

extern "C" void kernel_launch(void* const* d_in, const int* in_sizes, int n_in,
                              void* d_out, int out_size)
{
    const float* x    = (const float*)d_in[0];
    const float* w    = (const float*)d_in[1];
    const float* bias = (const float*)d_in[2];
    float* out = (float*)d_out;

    cudaFuncSetAttribute(qconv2d_kernel,
                         cudaFuncAttributeMaxDynamicSharedMemorySize,
                         SMEM_BYTES);

    dim3 grid(56, 8);   // (output row, batch pair)
    qconv2d_kernel<<<grid, TB, SMEM_BYTES>>>(x, w, bias, out);
}